// round 16
// baseline (speedup 1.0000x reference)
#include <cuda_runtime.h>
#include <cuda_fp16.h>
#include <math.h>
#include <stdint.h>

// ---------------------------------------------------------------------------
// GPT-2-style MQA transformer forward.
//   L=4, H=1024, N=16 heads, D=64, I=4096, B=2, S=2048.
// GEMMs: mma.sync fp16, weight split-2 (wh+wl pre-split), activations fp16.
//   All k16-step fragment loads hoisted ahead of the 32 MMAs (one LDS latency
//   per k-step instead of four); same-acc MMA distance 16.
//   3-stage cp.async pipeline, fill-after-MMA, 2 CTAs/SM.
// Attention: fp32 SIMT flash kernel with packed f32x2 FFMA + longest-first.
// LN: single-pass sum/sumsq with shuffle reduction (1 barrier).
// ---------------------------------------------------------------------------

#define LL 4
#define HH 1024
#define DD 64
#define NHEAD 16
#define II 4096
#define BB 2
#define SS 2048
#define QKVW (HH + 2 * DD)      // 1152
#define MTOK (BB * SS)          // 4096
#define LN_EPS 1e-5f

typedef unsigned long long u64;

// ------------------------- scratch (static device mem) ---------------------
__device__ float g_h  [(size_t)MTOK * HH];     // residual stream (fp32)
__device__ float g_qkv[(size_t)MTOK * QKVW];   // qkv projection (fp32)

// pre-split weights (hi/lo fp16; hi+lo ~= fp32 weight)
__device__ __half g_wq_h[(size_t)LL * QKVW * HH], g_wq_l[(size_t)LL * QKVW * HH];
__device__ __half g_wc_h[(size_t)LL * HH * HH],   g_wc_l[(size_t)LL * HH * HH];
__device__ __half g_wf_h[(size_t)LL * II * HH],   g_wf_l[(size_t)LL * II * HH];
__device__ __half g_wm_h[(size_t)LL * HH * II],   g_wm_l[(size_t)LL * HH * II];

// fp16 activations (single precision copy)
__device__ __half g_x16 [(size_t)MTOK * HH];   // LN out
__device__ __half g_at16[(size_t)MTOK * HH];   // attn out
__device__ __half g_m16 [(size_t)MTOK * II];   // MLP hidden

// segment sizes (in float4 units) for the fused split kernel
#define NQ4 ((LL * QKVW * HH) / 4)
#define NC4 ((LL * HH * HH) / 4)
#define NF4 ((LL * II * HH) / 4)
#define NM4 ((LL * HH * II) / 4)
#define NTOT4 (NQ4 + NC4 + NF4 + NM4)

// ----------------------------- PTX helpers ---------------------------------
__device__ __forceinline__ uint32_t smem_u32(const void* p) {
    uint32_t a;
    asm("{ .reg .u64 t; cvta.to.shared.u64 t, %1; cvt.u32.u64 %0, t; }"
        : "=r"(a) : "l"(p));
    return a;
}
__device__ __forceinline__ void ldsm4(uint32_t* r, uint32_t addr) {
    asm volatile("ldmatrix.sync.aligned.m8n8.x4.shared.b16 {%0,%1,%2,%3}, [%4];"
        : "=r"(r[0]), "=r"(r[1]), "=r"(r[2]), "=r"(r[3]) : "r"(addr));
}
// non-volatile: pure register computation; ptxas may schedule freely
__device__ __forceinline__ void mma_f16(float* d, const uint32_t* a,
                                        uint32_t b0, uint32_t b1) {
    asm("mma.sync.aligned.m16n8k16.row.col.f32.f16.f16.f32 "
        "{%0,%1,%2,%3}, {%4,%5,%6,%7}, {%8,%9}, {%0,%1,%2,%3};"
        : "+f"(d[0]), "+f"(d[1]), "+f"(d[2]), "+f"(d[3])
        : "r"(a[0]), "r"(a[1]), "r"(a[2]), "r"(a[3]), "r"(b0), "r"(b1));
}
__device__ __forceinline__ void cp16(uint32_t dst, const void* src) {
    asm volatile("cp.async.ca.shared.global [%0], [%1], 16;"
                 :: "r"(dst), "l"(src) : "memory");
}
#define CP_COMMIT() asm volatile("cp.async.commit_group;" ::: "memory")
#define CP_WAIT1()  asm volatile("cp.async.wait_group 1;" ::: "memory")

// packed f32x2 ops (sm_100+ base ISA)
__device__ __forceinline__ u64 pack2(float x, float y) {
    u64 r; asm("mov.b64 %0, {%1, %2};" : "=l"(r) : "f"(x), "f"(y)); return r;
}
__device__ __forceinline__ void unpack2(u64 v, float& x, float& y) {
    asm("mov.b64 {%0, %1}, %2;" : "=f"(x), "=f"(y) : "l"(v));
}
__device__ __forceinline__ void ffma2(u64& d, u64 a, u64 b) {
    asm("fma.rn.f32x2 %0, %1, %2, %0;" : "+l"(d) : "l"(a), "l"(b));
}
__device__ __forceinline__ void fadd2(u64& d, u64 a) {
    asm("add.rn.f32x2 %0, %0, %1;" : "+l"(d) : "l"(a));
}
__device__ __forceinline__ void fmul2(u64& d, u64 a) {
    asm("mul.rn.f32x2 %0, %0, %1;" : "+l"(d) : "l"(a));
}

// pack two fp32 -> one u32 of fp16x2
__device__ __forceinline__ uint32_t h2pack(float x, float y) {
    __half hx = __float2half(x), hy = __float2half(y);
    return (uint32_t)*reinterpret_cast<unsigned short*>(&hx)
         | ((uint32_t)*reinterpret_cast<unsigned short*>(&hy) << 16);
}
// fp32 pair -> fp16 hi pair + fp16 lo pair (weight split)
__device__ __forceinline__ void split_pair_h(float x, float y,
                                             uint32_t& hi, uint32_t& lo) {
    __half hx = __float2half(x), hy = __float2half(y);
    float lx = x - __half2float(hx);
    float ly = y - __half2float(hy);
    __half gx = __float2half(lx), gy = __float2half(ly);
    hi = (uint32_t)*reinterpret_cast<unsigned short*>(&hx)
       | ((uint32_t)*reinterpret_cast<unsigned short*>(&hy) << 16);
    lo = (uint32_t)*reinterpret_cast<unsigned short*>(&gx)
       | ((uint32_t)*reinterpret_cast<unsigned short*>(&gy) << 16);
}

// ------------- fused weight split (fp32 -> fp16 hi/lo, all 4 mats) ----------
__global__ void split_all_kernel(const float* __restrict__ wq,
                                 const float* __restrict__ wc,
                                 const float* __restrict__ wf,
                                 const float* __restrict__ wm,
                                 __half* __restrict__ qh, __half* __restrict__ ql,
                                 __half* __restrict__ ch, __half* __restrict__ cl,
                                 __half* __restrict__ fh, __half* __restrict__ fl,
                                 __half* __restrict__ mh, __half* __restrict__ ml)
{
    int i = blockIdx.x * blockDim.x + threadIdx.x;   // global float4 index
    const float* s; __half *hp, *lp; int j;
    if (i < NQ4)                   { s = wq; hp = qh; lp = ql; j = i; }
    else if (i < NQ4 + NC4)        { s = wc; hp = ch; lp = cl; j = i - NQ4; }
    else if (i < NQ4 + NC4 + NF4)  { s = wf; hp = fh; lp = fl; j = i - NQ4 - NC4; }
    else                           { s = wm; hp = mh; lp = ml; j = i - NQ4 - NC4 - NF4; }
    float4 v = ((const float4*)s)[j];
    uint32_t h01, l01, h23, l23;
    split_pair_h(v.x, v.y, h01, l01);
    split_pair_h(v.z, v.w, h23, l23);
    ((uint2*)hp)[j] = make_uint2(h01, h23);
    ((uint2*)lp)[j] = make_uint2(l01, l23);
}

// ----------------------------- embedding -----------------------------------
__global__ void embed_kernel(const int* __restrict__ ids,
                             const int* __restrict__ pos,
                             const float* __restrict__ wte,
                             const float* __restrict__ wpe,
                             float* __restrict__ out)
{
    int row = blockIdx.x;
    int t   = threadIdx.x;
    int id  = ids[row];
    int p   = pos[row];
    const float4* a = (const float4*)(wte + (size_t)id * HH);
    const float4* b = (const float4*)(wpe + (size_t)p  * HH);
    float4 va = a[t], vb = b[t];
    ((float4*)(out + (size_t)row * HH))[t] =
        make_float4(va.x + vb.x, va.y + vb.y, va.z + vb.z, va.w + vb.w);
}

// ----------------------------- layernorm ------------------------------------
template<bool TO16>
__global__ void ln_kernel(const float* __restrict__ x,
                          const float* __restrict__ w,
                          const float* __restrict__ b,
                          __half* __restrict__ y16,
                          float* __restrict__ y32)
{
    int row  = blockIdx.x;
    int t    = threadIdx.x;
    int lane = t & 31;
    int wrp  = t >> 5;
    __shared__ float r1[8], r2[8];

    float4 v = ((const float4*)(x + (size_t)row * HH))[t];
    float s1 = v.x + v.y + v.z + v.w;
    float s2 = v.x * v.x + v.y * v.y + v.z * v.z + v.w * v.w;
    #pragma unroll
    for (int o = 16; o > 0; o >>= 1) {
        s1 += __shfl_xor_sync(0xFFFFFFFFu, s1, o);
        s2 += __shfl_xor_sync(0xFFFFFFFFu, s2, o);
    }
    if (lane == 0) { r1[wrp] = s1; r2[wrp] = s2; }
    __syncthreads();
    float t1 = 0.0f, t2 = 0.0f;
    #pragma unroll
    for (int i = 0; i < 8; i++) { t1 += r1[i]; t2 += r2[i]; }
    float mu   = t1 * (1.0f / HH);
    float var  = t2 * (1.0f / HH) - mu * mu;
    float rstd = rsqrtf(var + LN_EPS);

    float4 ww  = ((const float4*)w)[t];
    float4 bb2 = ((const float4*)b)[t];
    float4 o4 = make_float4((v.x - mu) * rstd * ww.x + bb2.x,
                            (v.y - mu) * rstd * ww.y + bb2.y,
                            (v.z - mu) * rstd * ww.z + bb2.z,
                            (v.w - mu) * rstd * ww.w + bb2.w);
    if (TO16) {
        ((uint2*)(y16 + (size_t)row * HH))[t] =
            make_uint2(h2pack(o4.x, o4.y), h2pack(o4.z, o4.w));
    } else {
        ((float4*)(y32 + (size_t)row * HH))[t] = o4;
    }
}

// ---------------------- fp16 weight-split-2 MMA GEMM ------------------------
// C = A @ (Wh+Wl)^T + bias;  A fp16 (activations), Wh/Wl fp16 (weight split).
// 2 MMAs per k-step. CTA: 128x128, 256 threads, 8 warps (4x2 -> 32x64/warp).
// Per k16-step: ALL 10 ldsm issued first, then 32 MMAs (hi-terms for all ni,
// then lo-terms) -> one LDS latency per step, same-acc distance 16.
// 3-stage cp.async pipeline, fill AFTER MMAs. K chunk = 32.
// MODE 0: C fp32.  MODE 1: C fp32 + resid.  MODE 2: gelu -> C16 fp16.
#define TILE_BYTES 8192                     // 128 x 32 fp16
#define STAGE_BYTES (3 * TILE_BYTES)        // A, Wh, Wl
#define GEMM_SMEM (3 * STAGE_BYTES)         // 73728

template<int MODE>
__global__ __launch_bounds__(256, 2)
void gemm_f16(const __half* __restrict__ A,
              const __half* __restrict__ Wh, const __half* __restrict__ Wl,
              const float* __restrict__ bias, const float* __restrict__ resid,
              float* __restrict__ C, __half* __restrict__ C16,
              int M, int Nn, int K)
{
    extern __shared__ char smem[];
    uint32_t sb = smem_u32(smem);

    int tid  = threadIdx.x;
    int lane = tid & 31;
    int wid  = tid >> 5;
    int wm   = wid >> 1;
    int wn   = wid & 1;
    int bm   = blockIdx.y * 128;
    int bn   = blockIdx.x * 128;

    auto fill = [&](int stage, int kb) {
        uint32_t base = sb + stage * STAGE_BYTES;
        #pragma unroll
        for (int s = 0; s < 2; s++) {
            int e   = tid + s * 256;          // 0..511
            int row = e >> 2;
            int seg = e & 3;
            uint32_t off = (uint32_t)row * 64 + ((seg ^ ((row >> 1) & 3)) << 4);
            size_t ga = (size_t)(bm + row) * K + kb + seg * 8;
            size_t gw = (size_t)(bn + row) * K + kb + seg * 8;
            cp16(base + 0 * TILE_BYTES + off, A  + ga);
            cp16(base + 1 * TILE_BYTES + off, Wh + gw);
            cp16(base + 2 * TILE_BYTES + off, Wl + gw);
        }
    };

    int maBase = (lane & 7) + ((lane >> 3) & 1) * 8;
    int kAhalf = lane >> 4;
    int nbBase = (lane & 7) + ((lane >> 4) & 1) * 8;
    int kBhalf = (lane >> 3) & 1;

    float acc[2][8][4];
    #pragma unroll
    for (int i = 0; i < 2; i++)
        #pragma unroll
        for (int j = 0; j < 8; j++)
            #pragma unroll
            for (int q = 0; q < 4; q++) acc[i][j][q] = 0.0f;

    const int T = K >> 5;
    fill(0, 0);  CP_COMMIT();
    fill(1, 32); CP_COMMIT();

    for (int t = 0; t < T; ++t) {
        CP_WAIT1();
        __syncthreads();

        uint32_t Ab  = sb + (t % 3) * STAGE_BYTES;
        uint32_t Whb = Ab + 1 * TILE_BYTES;
        uint32_t Wlb = Ab + 2 * TILE_BYTES;

        #pragma unroll
        for (int kt = 0; kt < 2; ++kt) {
            int kcA = kt * 2 + kAhalf;
            int kcB = kt * 2 + kBhalf;

            // ---- hoisted fragment loads: 10 back-to-back ldsm ----
            uint32_t af[2][4];
            uint32_t bh[4][4], bl[4][4];
            #pragma unroll
            for (int mi = 0; mi < 2; mi++) {
                int m = wm * 32 + mi * 16 + maBase;
                uint32_t off = (uint32_t)m * 64 + ((kcA ^ ((m >> 1) & 3)) << 4);
                ldsm4(af[mi], Ab + off);
            }
            #pragma unroll
            for (int ni = 0; ni < 4; ni++) {
                int n = wn * 64 + ni * 16 + nbBase;
                uint32_t off = (uint32_t)n * 64 + ((kcB ^ ((n >> 1) & 3)) << 4);
                ldsm4(bh[ni], Whb + off);
                ldsm4(bl[ni], Wlb + off);
            }

            // ---- 32 MMAs: hi terms for all ni, then lo terms ----
            #pragma unroll
            for (int ni = 0; ni < 4; ni++) {
                mma_f16(acc[0][ni * 2 + 0], af[0], bh[ni][0], bh[ni][1]);
                mma_f16(acc[0][ni * 2 + 1], af[0], bh[ni][2], bh[ni][3]);
                mma_f16(acc[1][ni * 2 + 0], af[1], bh[ni][0], bh[ni][1]);
                mma_f16(acc[1][ni * 2 + 1], af[1], bh[ni][2], bh[ni][3]);
            }
            #pragma unroll
            for (int ni = 0; ni < 4; ni++) {
                mma_f16(acc[0][ni * 2 + 0], af[0], bl[ni][0], bl[ni][1]);
                mma_f16(acc[0][ni * 2 + 1], af[0], bl[ni][2], bl[ni][3]);
                mma_f16(acc[1][ni * 2 + 0], af[1], bl[ni][0], bl[ni][1]);
                mma_f16(acc[1][ni * 2 + 1], af[1], bl[ni][2], bl[ni][3]);
            }
        }

        if (t + 2 < T) fill((t + 2) % 3, (t + 2) * 32);
        CP_COMMIT();
    }

    // ------------------------------ epilogue --------------------------------
    int g     = lane >> 2;
    int cpair = (lane & 3) * 2;
    #pragma unroll
    for (int mi = 0; mi < 2; mi++) {
        #pragma unroll
        for (int j = 0; j < 8; j++) {
            int col = bn + wn * 64 + (j >> 1) * 16 + (j & 1) * 8 + cpair;
            int r0  = bm + wm * 32 + mi * 16 + g;
            float b0 = bias[col], b1 = bias[col + 1];
            #pragma unroll
            for (int hrow = 0; hrow < 2; hrow++) {
                int row = r0 + hrow * 8;
                float v0 = acc[mi][j][hrow * 2 + 0] + b0;
                float v1 = acc[mi][j][hrow * 2 + 1] + b1;
                if (MODE == 2) {
                    v0 = 0.5f * v0 * (1.0f + erff(v0 * 0.70710678118654752f));
                    v1 = 0.5f * v1 * (1.0f + erff(v1 * 0.70710678118654752f));
                    *(uint32_t*)(C16 + (size_t)row * Nn + col) = h2pack(v0, v1);
                } else {
                    if (MODE == 1) {
                        const float* rr = resid + (size_t)row * Nn + col;
                        v0 += rr[0]; v1 += rr[1];
                    }
                    *(float2*)(C + (size_t)row * Nn + col) = make_float2(v0, v1);
                }
            }
        }
    }
}

// ------------------------------ attention -----------------------------------
// MQA causal flash attention, fp32 SIMT with packed f32x2 math.
// 1 query per thread, 128 threads. Longest-first block scheduling.
// Output written as fp16.
__global__ __launch_bounds__(128)
void attn_kernel(const float* __restrict__ qkv, __half* __restrict__ o16)
{
    __shared__ float Ks[64][64];
    __shared__ float Vs[64][64];

    int q0    = ((int)gridDim.x - 1 - (int)blockIdx.x) * 128;  // longest first
    int head  = blockIdx.y;
    int batch = blockIdx.z;
    int tid   = threadIdx.x;
    int qi    = q0 + tid;

    const float* base = qkv + (size_t)batch * SS * QKVW;

    u64 q2[32];
    {
        const float* qrow = base + (size_t)qi * QKVW + head * DD;
        #pragma unroll
        for (int d = 0; d < 64; d += 4) {
            float4 v = *(const float4*)(qrow + d);
            q2[d / 2]     = pack2(v.x * 0.125f, v.y * 0.125f);
            q2[d / 2 + 1] = pack2(v.z * 0.125f, v.w * 0.125f);
        }
    }

    u64 acc2[32];
    #pragma unroll
    for (int d = 0; d < 32; d++) acc2[d] = 0ULL;
    float m = -INFINITY, l = 0.0f;

    int nt = q0 / 64 + 2;
    for (int kt = 0; kt < nt; ++kt) {
        int k0 = kt * 64;
        for (int f = tid; f < 1024; f += 128) {
            int j  = f >> 4;
            int dd = (f & 15) << 2;
            const float* kr = base + (size_t)(k0 + j) * QKVW + HH;
            *(float4*)&Ks[j][dd] = *(const float4*)(kr + dd);
            *(float4*)&Vs[j][dd] = *(const float4*)(kr + DD + dd);
        }
        __syncthreads();

        #pragma unroll 1
        for (int sb2 = 0; sb2 < 64; sb2 += 16) {
            float s[16];
            float mt = -INFINITY;
            #pragma unroll
            for (int jj = 0; jj < 16; ++jj) {
                int j = sb2 + jj;
                const u64* kr2 = (const u64*)&Ks[j][0];
                u64 p0 = 0ULL, p1 = 0ULL, p2 = 0ULL, p3 = 0ULL;
                #pragma unroll
                for (int d = 0; d < 32; d += 4) {
                    ffma2(p0, q2[d],     kr2[d]);
                    ffma2(p1, q2[d + 1], kr2[d + 1]);
                    ffma2(p2, q2[d + 2], kr2[d + 2]);
                    ffma2(p3, q2[d + 3], kr2[d + 3]);
                }
                fadd2(p0, p1);
                fadd2(p2, p3);
                fadd2(p0, p2);
                float dx, dy; unpack2(p0, dx, dy);
                float dot = dx + dy;
                s[jj] = (k0 + j <= qi) ? dot : -INFINITY;
                mt = fmaxf(mt, s[jj]);
            }
            if (mt != -INFINITY) {
                float mn = fmaxf(m, mt);
                float c  = __expf(m - mn);
                float psum = 0.0f;
                #pragma unroll
                for (int jj = 0; jj < 16; ++jj) {
                    s[jj] = __expf(s[jj] - mn);
                    psum += s[jj];
                }
                l = l * c + psum;
                u64 c2 = pack2(c, c);
                #pragma unroll
                for (int d = 0; d < 32; d++) fmul2(acc2[d], c2);
                #pragma unroll
                for (int jj = 0; jj < 16; ++jj) {
                    u64 pj2 = pack2(s[jj], s[jj]);
                    const u64* vr2 = (const u64*)&Vs[sb2 + jj][0];
                    #pragma unroll
                    for (int d = 0; d < 32; d++) ffma2(acc2[d], pj2, vr2[d]);
                }
                m = mn;
            }
        }
        __syncthreads();
    }

    float inv = 1.0f / l;
    size_t obase = (size_t)(batch * SS + qi) * HH + head * DD;
    #pragma unroll
    for (int d = 0; d < 32; d += 2) {
        float a0, a1, a2, a3;
        unpack2(acc2[d],     a0, a1);
        unpack2(acc2[d + 1], a2, a3);
        *(uint2*)(o16 + obase + 2 * d) =
            make_uint2(h2pack(a0 * inv, a1 * inv), h2pack(a2 * inv, a3 * inv));
    }
}

// ------------------------------- driver -------------------------------------
extern "C" void kernel_launch(void* const* d_in, const int* in_sizes, int n_in,
                              void* d_out, int out_size)
{
    const int*   ids     = (const int*)  d_in[0];
    const int*   pos     = (const int*)  d_in[1];
    const float* wte     = (const float*)d_in[2];
    const float* wpe     = (const float*)d_in[3];
    const float* ln1_w   = (const float*)d_in[4];
    const float* ln1_b   = (const float*)d_in[5];
    const float* cattn_w = (const float*)d_in[6];
    const float* cattn_b = (const float*)d_in[7];
    const float* cproj_w = (const float*)d_in[8];
    const float* cproj_b = (const float*)d_in[9];
    const float* ln2_w   = (const float*)d_in[10];
    const float* ln2_b   = (const float*)d_in[11];
    const float* fc_w    = (const float*)d_in[12];
    const float* fc_b    = (const float*)d_in[13];
    const float* mproj_w = (const float*)d_in[14];
    const float* mproj_b = (const float*)d_in[15];
    const float* lnf_w   = (const float*)d_in[16];
    const float* lnf_b   = (const float*)d_in[17];
    float* out = (float*)d_out;

    float *h, *qkv;
    __half *wq_h, *wq_l, *wc_h, *wc_l, *wf_h, *wf_l, *wm_h, *wm_l;
    __half *x16, *at16, *m16;
    cudaGetSymbolAddress((void**)&h,    g_h);
    cudaGetSymbolAddress((void**)&qkv,  g_qkv);
    cudaGetSymbolAddress((void**)&wq_h, g_wq_h); cudaGetSymbolAddress((void**)&wq_l, g_wq_l);
    cudaGetSymbolAddress((void**)&wc_h, g_wc_h); cudaGetSymbolAddress((void**)&wc_l, g_wc_l);
    cudaGetSymbolAddress((void**)&wf_h, g_wf_h); cudaGetSymbolAddress((void**)&wf_l, g_wf_l);
    cudaGetSymbolAddress((void**)&wm_h, g_wm_h); cudaGetSymbolAddress((void**)&wm_l, g_wm_l);
    cudaGetSymbolAddress((void**)&x16,  g_x16);
    cudaGetSymbolAddress((void**)&at16, g_at16);
    cudaGetSymbolAddress((void**)&m16,  g_m16);

    cudaFuncSetAttribute(gemm_f16<0>, cudaFuncAttributeMaxDynamicSharedMemorySize, GEMM_SMEM);
    cudaFuncSetAttribute(gemm_f16<1>, cudaFuncAttributeMaxDynamicSharedMemorySize, GEMM_SMEM);
    cudaFuncSetAttribute(gemm_f16<2>, cudaFuncAttributeMaxDynamicSharedMemorySize, GEMM_SMEM);

    // fused weight split (one launch; ~70us of pure bandwidth)
    split_all_kernel<<<NTOT4 / 256, 256>>>(cattn_w, cproj_w, fc_w, mproj_w,
                                           wq_h, wq_l, wc_h, wc_l,
                                           wf_h, wf_l, wm_h, wm_l);

    embed_kernel<<<MTOK, 256>>>(ids, pos, wte, wpe, h);

    for (int l = 0; l < LL; ++l) {
        ln_kernel<true><<<MTOK, 256>>>(h, ln1_w + (size_t)l * HH,
                                       ln1_b + (size_t)l * HH, x16, nullptr);

        gemm_f16<0><<<dim3(QKVW / 128, MTOK / 128), 256, GEMM_SMEM>>>(
            x16, wq_h + (size_t)l * QKVW * HH, wq_l + (size_t)l * QKVW * HH,
            cattn_b + (size_t)l * QKVW, nullptr, qkv, nullptr,
            MTOK, QKVW, HH);

        attn_kernel<<<dim3(SS / 128, NHEAD, BB), 128>>>(qkv, at16);

        gemm_f16<1><<<dim3(HH / 128, MTOK / 128), 256, GEMM_SMEM>>>(
            at16, wc_h + (size_t)l * HH * HH, wc_l + (size_t)l * HH * HH,
            cproj_b + (size_t)l * HH, h, h, nullptr,
            MTOK, HH, HH);

        ln_kernel<true><<<MTOK, 256>>>(h, ln2_w + (size_t)l * HH,
                                       ln2_b + (size_t)l * HH, x16, nullptr);

        gemm_f16<2><<<dim3(II / 128, MTOK / 128), 256, GEMM_SMEM>>>(
            x16, wf_h + (size_t)l * II * HH, wf_l + (size_t)l * II * HH,
            fc_b + (size_t)l * II, nullptr, nullptr, m16,
            MTOK, II, HH);

        gemm_f16<1><<<dim3(HH / 128, MTOK / 128), 256, GEMM_SMEM>>>(
            m16, wm_h + (size_t)l * HH * II, wm_l + (size_t)l * HH * II,
            mproj_b + (size_t)l * HH, h, h, nullptr,
            MTOK, HH, II);
    }

    ln_kernel<false><<<MTOK, 256>>>(h, lnf_w, lnf_b, nullptr, out);
}

// round 17
// speedup vs baseline: 2.3888x; 2.3888x over previous
#include <cuda_runtime.h>
#include <cuda_fp16.h>
#include <math.h>
#include <stdint.h>

// ---------------------------------------------------------------------------
// GPT-2-style MQA transformer forward.
//   L=4, H=1024, N=16 heads, D=64, I=4096, B=2, S=2048.
// GEMMs: mma.sync fp16, weight split-2; activations fp16; R14 inner loop.
// Attention: tensor-core flash attention (fp16 QK^T and PV, fp32 softmax).
// LN: single-pass sum/sumsq with shuffle reduction.
// ---------------------------------------------------------------------------

#define LL 4
#define HH 1024
#define DD 64
#define NHEAD 16
#define II 4096
#define BB 2
#define SS 2048
#define QKVW (HH + 2 * DD)      // 1152
#define MTOK (BB * SS)          // 4096
#define LN_EPS 1e-5f

typedef unsigned long long u64;

// ------------------------- scratch (static device mem) ---------------------
__device__ float g_h[(size_t)MTOK * HH];       // residual stream (fp32)

// pre-split weights (hi/lo fp16; hi+lo ~= fp32 weight)
__device__ __half g_wq_h[(size_t)LL * QKVW * HH], g_wq_l[(size_t)LL * QKVW * HH];
__device__ __half g_wc_h[(size_t)LL * HH * HH],   g_wc_l[(size_t)LL * HH * HH];
__device__ __half g_wf_h[(size_t)LL * II * HH],   g_wf_l[(size_t)LL * II * HH];
__device__ __half g_wm_h[(size_t)LL * HH * II],   g_wm_l[(size_t)LL * HH * II];

// fp16 activations
__device__ __half g_x16 [(size_t)MTOK * HH];   // LN out
__device__ __half g_at16[(size_t)MTOK * HH];   // attn out
__device__ __half g_m16 [(size_t)MTOK * II];   // MLP hidden
__device__ __half g_q16 [(size_t)MTOK * HH];   // queries (x0.125 folded)
__device__ __half g_k16 [(size_t)MTOK * DD];   // keys
__device__ __half g_v16 [(size_t)MTOK * DD];   // values

// segment sizes (in float4 units) for the fused split kernel
#define NQ4 ((LL * QKVW * HH) / 4)
#define NC4 ((LL * HH * HH) / 4)
#define NF4 ((LL * II * HH) / 4)
#define NM4 ((LL * HH * II) / 4)
#define NTOT4 (NQ4 + NC4 + NF4 + NM4)

// ----------------------------- PTX helpers ---------------------------------
__device__ __forceinline__ uint32_t smem_u32(const void* p) {
    uint32_t a;
    asm("{ .reg .u64 t; cvta.to.shared.u64 t, %1; cvt.u32.u64 %0, t; }"
        : "=r"(a) : "l"(p));
    return a;
}
__device__ __forceinline__ void ldsm4(uint32_t* r, uint32_t addr) {
    asm volatile("ldmatrix.sync.aligned.m8n8.x4.shared.b16 {%0,%1,%2,%3}, [%4];"
        : "=r"(r[0]), "=r"(r[1]), "=r"(r[2]), "=r"(r[3]) : "r"(addr));
}
__device__ __forceinline__ void ldsm4t(uint32_t* r, uint32_t addr) {
    asm volatile("ldmatrix.sync.aligned.m8n8.x4.trans.shared.b16 {%0,%1,%2,%3}, [%4];"
        : "=r"(r[0]), "=r"(r[1]), "=r"(r[2]), "=r"(r[3]) : "r"(addr));
}
__device__ __forceinline__ void mma_f16(float* d, const uint32_t* a,
                                        uint32_t b0, uint32_t b1) {
    asm("mma.sync.aligned.m16n8k16.row.col.f32.f16.f16.f32 "
        "{%0,%1,%2,%3}, {%4,%5,%6,%7}, {%8,%9}, {%0,%1,%2,%3};"
        : "+f"(d[0]), "+f"(d[1]), "+f"(d[2]), "+f"(d[3])
        : "r"(a[0]), "r"(a[1]), "r"(a[2]), "r"(a[3]), "r"(b0), "r"(b1));
}
__device__ __forceinline__ void cp16(uint32_t dst, const void* src) {
    asm volatile("cp.async.ca.shared.global [%0], [%1], 16;"
                 :: "r"(dst), "l"(src) : "memory");
}
#define CP_COMMIT() asm volatile("cp.async.commit_group;" ::: "memory")
#define CP_WAIT1()  asm volatile("cp.async.wait_group 1;" ::: "memory")
#define CP_WAIT0()  asm volatile("cp.async.wait_group 0;" ::: "memory")

// pack two fp32 -> one u32 of fp16x2
__device__ __forceinline__ uint32_t h2pack(float x, float y) {
    __half hx = __float2half(x), hy = __float2half(y);
    return (uint32_t)*reinterpret_cast<unsigned short*>(&hx)
         | ((uint32_t)*reinterpret_cast<unsigned short*>(&hy) << 16);
}
// fp32 pair -> fp16 hi pair + fp16 lo pair (weight split)
__device__ __forceinline__ void split_pair_h(float x, float y,
                                             uint32_t& hi, uint32_t& lo) {
    __half hx = __float2half(x), hy = __float2half(y);
    float lx = x - __half2float(hx);
    float ly = y - __half2float(hy);
    __half gx = __float2half(lx), gy = __float2half(ly);
    hi = (uint32_t)*reinterpret_cast<unsigned short*>(&hx)
       | ((uint32_t)*reinterpret_cast<unsigned short*>(&hy) << 16);
    lo = (uint32_t)*reinterpret_cast<unsigned short*>(&gx)
       | ((uint32_t)*reinterpret_cast<unsigned short*>(&gy) << 16);
}

// ------------- fused weight split (fp32 -> fp16 hi/lo, all 4 mats) ----------
__global__ void split_all_kernel(const float* __restrict__ wq,
                                 const float* __restrict__ wc,
                                 const float* __restrict__ wf,
                                 const float* __restrict__ wm,
                                 __half* __restrict__ qh, __half* __restrict__ ql,
                                 __half* __restrict__ ch, __half* __restrict__ cl,
                                 __half* __restrict__ fh, __half* __restrict__ fl,
                                 __half* __restrict__ mh, __half* __restrict__ ml)
{
    int i = blockIdx.x * blockDim.x + threadIdx.x;   // global float4 index
    const float* s; __half *hp, *lp; int j;
    if (i < NQ4)                   { s = wq; hp = qh; lp = ql; j = i; }
    else if (i < NQ4 + NC4)        { s = wc; hp = ch; lp = cl; j = i - NQ4; }
    else if (i < NQ4 + NC4 + NF4)  { s = wf; hp = fh; lp = fl; j = i - NQ4 - NC4; }
    else                           { s = wm; hp = mh; lp = ml; j = i - NQ4 - NC4 - NF4; }
    float4 v = ((const float4*)s)[j];
    uint32_t h01, l01, h23, l23;
    split_pair_h(v.x, v.y, h01, l01);
    split_pair_h(v.z, v.w, h23, l23);
    ((uint2*)hp)[j] = make_uint2(h01, h23);
    ((uint2*)lp)[j] = make_uint2(l01, l23);
}

// ----------------------------- embedding -----------------------------------
__global__ void embed_kernel(const int* __restrict__ ids,
                             const int* __restrict__ pos,
                             const float* __restrict__ wte,
                             const float* __restrict__ wpe,
                             float* __restrict__ out)
{
    int row = blockIdx.x;
    int t   = threadIdx.x;
    int id  = ids[row];
    int p   = pos[row];
    const float4* a = (const float4*)(wte + (size_t)id * HH);
    const float4* b = (const float4*)(wpe + (size_t)p  * HH);
    float4 va = a[t], vb = b[t];
    ((float4*)(out + (size_t)row * HH))[t] =
        make_float4(va.x + vb.x, va.y + vb.y, va.z + vb.z, va.w + vb.w);
}

// ----------------------------- layernorm ------------------------------------
template<bool TO16>
__global__ void ln_kernel(const float* __restrict__ x,
                          const float* __restrict__ w,
                          const float* __restrict__ b,
                          __half* __restrict__ y16,
                          float* __restrict__ y32)
{
    int row  = blockIdx.x;
    int t    = threadIdx.x;
    int lane = t & 31;
    int wrp  = t >> 5;
    __shared__ float r1[8], r2[8];

    float4 v = ((const float4*)(x + (size_t)row * HH))[t];
    float s1 = v.x + v.y + v.z + v.w;
    float s2 = v.x * v.x + v.y * v.y + v.z * v.z + v.w * v.w;
    #pragma unroll
    for (int o = 16; o > 0; o >>= 1) {
        s1 += __shfl_xor_sync(0xFFFFFFFFu, s1, o);
        s2 += __shfl_xor_sync(0xFFFFFFFFu, s2, o);
    }
    if (lane == 0) { r1[wrp] = s1; r2[wrp] = s2; }
    __syncthreads();
    float t1 = 0.0f, t2 = 0.0f;
    #pragma unroll
    for (int i = 0; i < 8; i++) { t1 += r1[i]; t2 += r2[i]; }
    float mu   = t1 * (1.0f / HH);
    float var  = t2 * (1.0f / HH) - mu * mu;
    float rstd = rsqrtf(var + LN_EPS);

    float4 ww  = ((const float4*)w)[t];
    float4 bb2 = ((const float4*)b)[t];
    float4 o4 = make_float4((v.x - mu) * rstd * ww.x + bb2.x,
                            (v.y - mu) * rstd * ww.y + bb2.y,
                            (v.z - mu) * rstd * ww.z + bb2.z,
                            (v.w - mu) * rstd * ww.w + bb2.w);
    if (TO16) {
        ((uint2*)(y16 + (size_t)row * HH))[t] =
            make_uint2(h2pack(o4.x, o4.y), h2pack(o4.z, o4.w));
    } else {
        ((float4*)(y32 + (size_t)row * HH))[t] = o4;
    }
}

// ---------------------- fp16 weight-split-2 MMA GEMM ------------------------
// C = A @ (Wh+Wl)^T + bias.  R14 inner loop (best measured).
// MODE 1: C fp32 + resid.  MODE 2: gelu -> C16 fp16.
// MODE 3: qkv epilogue -> q16 (x0.125, cols<1024), k16, v16 fp16.
#define TILE_BYTES 8192                     // 128 x 32 fp16
#define STAGE_BYTES (3 * TILE_BYTES)        // A, Wh, Wl
#define GEMM_SMEM (3 * STAGE_BYTES)         // 73728

template<int MODE>
__global__ __launch_bounds__(256, 2)
void gemm_f16(const __half* __restrict__ A,
              const __half* __restrict__ Wh, const __half* __restrict__ Wl,
              const float* __restrict__ bias, const float* __restrict__ resid,
              float* __restrict__ C, __half* __restrict__ C16,
              __half* __restrict__ K16, __half* __restrict__ V16,
              int M, int Nn, int K)
{
    extern __shared__ char smem[];
    uint32_t sb = smem_u32(smem);

    int tid  = threadIdx.x;
    int lane = tid & 31;
    int wid  = tid >> 5;
    int wm   = wid >> 1;
    int wn   = wid & 1;
    int bm   = blockIdx.y * 128;
    int bn   = blockIdx.x * 128;

    auto fill = [&](int stage, int kb) {
        uint32_t base = sb + stage * STAGE_BYTES;
        #pragma unroll
        for (int s = 0; s < 2; s++) {
            int e   = tid + s * 256;          // 0..511
            int row = e >> 2;
            int seg = e & 3;
            uint32_t off = (uint32_t)row * 64 + ((seg ^ ((row >> 1) & 3)) << 4);
            size_t ga = (size_t)(bm + row) * K + kb + seg * 8;
            size_t gw = (size_t)(bn + row) * K + kb + seg * 8;
            cp16(base + 0 * TILE_BYTES + off, A  + ga);
            cp16(base + 1 * TILE_BYTES + off, Wh + gw);
            cp16(base + 2 * TILE_BYTES + off, Wl + gw);
        }
    };

    int maBase = (lane & 7) + ((lane >> 3) & 1) * 8;
    int kAhalf = lane >> 4;
    int nbBase = (lane & 7) + ((lane >> 4) & 1) * 8;
    int kBhalf = (lane >> 3) & 1;

    float acc[2][8][4];
    #pragma unroll
    for (int i = 0; i < 2; i++)
        #pragma unroll
        for (int j = 0; j < 8; j++)
            #pragma unroll
            for (int q = 0; q < 4; q++) acc[i][j][q] = 0.0f;

    const int T = K >> 5;
    fill(0, 0);  CP_COMMIT();
    fill(1, 32); CP_COMMIT();

    for (int t = 0; t < T; ++t) {
        CP_WAIT1();
        __syncthreads();

        uint32_t Ab  = sb + (t % 3) * STAGE_BYTES;
        uint32_t Whb = Ab + 1 * TILE_BYTES;
        uint32_t Wlb = Ab + 2 * TILE_BYTES;

        #pragma unroll
        for (int kt = 0; kt < 2; ++kt) {
            int kcA = kt * 2 + kAhalf;
            int kcB = kt * 2 + kBhalf;

            uint32_t af[2][4];
            #pragma unroll
            for (int mi = 0; mi < 2; mi++) {
                int m = wm * 32 + mi * 16 + maBase;
                uint32_t off = (uint32_t)m * 64 + ((kcA ^ ((m >> 1) & 3)) << 4);
                ldsm4(af[mi], Ab + off);
            }

            #pragma unroll
            for (int ni = 0; ni < 4; ni++) {
                int n = wn * 64 + ni * 16 + nbBase;
                uint32_t off = (uint32_t)n * 64 + ((kcB ^ ((n >> 1) & 3)) << 4);
                uint32_t bh[4], bl[4];
                ldsm4(bh, Whb + off);
                ldsm4(bl, Wlb + off);
                mma_f16(acc[0][ni * 2 + 0], af[0], bh[0], bh[1]);
                mma_f16(acc[0][ni * 2 + 1], af[0], bh[2], bh[3]);
                mma_f16(acc[1][ni * 2 + 0], af[1], bh[0], bh[1]);
                mma_f16(acc[1][ni * 2 + 1], af[1], bh[2], bh[3]);
                mma_f16(acc[0][ni * 2 + 0], af[0], bl[0], bl[1]);
                mma_f16(acc[0][ni * 2 + 1], af[0], bl[2], bl[3]);
                mma_f16(acc[1][ni * 2 + 0], af[1], bl[0], bl[1]);
                mma_f16(acc[1][ni * 2 + 1], af[1], bl[2], bl[3]);
            }
        }

        if (t + 2 < T) fill((t + 2) % 3, (t + 2) * 32);
        CP_COMMIT();
    }

    // ------------------------------ epilogue --------------------------------
    int g     = lane >> 2;
    int cpair = (lane & 3) * 2;
    #pragma unroll
    for (int mi = 0; mi < 2; mi++) {
        #pragma unroll
        for (int j = 0; j < 8; j++) {
            int col = bn + wn * 64 + (j >> 1) * 16 + (j & 1) * 8 + cpair;
            int r0  = bm + wm * 32 + mi * 16 + g;
            float b0 = bias[col], b1 = bias[col + 1];
            #pragma unroll
            for (int hrow = 0; hrow < 2; hrow++) {
                int row = r0 + hrow * 8;
                float v0 = acc[mi][j][hrow * 2 + 0] + b0;
                float v1 = acc[mi][j][hrow * 2 + 1] + b1;
                if (MODE == 2) {
                    v0 = 0.5f * v0 * (1.0f + erff(v0 * 0.70710678118654752f));
                    v1 = 0.5f * v1 * (1.0f + erff(v1 * 0.70710678118654752f));
                    *(uint32_t*)(C16 + (size_t)row * Nn + col) = h2pack(v0, v1);
                } else if (MODE == 3) {
                    if (col < HH) {
                        *(uint32_t*)(C16 + (size_t)row * HH + col) =
                            h2pack(v0 * 0.125f, v1 * 0.125f);
                    } else if (col < HH + DD) {
                        *(uint32_t*)(K16 + (size_t)row * DD + (col - HH)) =
                            h2pack(v0, v1);
                    } else {
                        *(uint32_t*)(V16 + (size_t)row * DD + (col - HH - DD)) =
                            h2pack(v0, v1);
                    }
                } else {
                    if (MODE == 1) {
                        const float* rr = resid + (size_t)row * Nn + col;
                        v0 += rr[0]; v1 += rr[1];
                    }
                    *(float2*)(C + (size_t)row * Nn + col) = make_float2(v0, v1);
                }
            }
        }
    }
}

// ------------------------ tensor-core flash attention -----------------------
// Block: 128 queries x 1 head x 1 batch, 256 threads (8 warps, 16 q each).
// S = Q K^T via mma (K non-trans ldsm), online softmax on fragments,
// O += P V via mma (V trans ldsm). Q pre-scaled by 0.125 in gemm<3>.
#define ATT_Q 0          // 128 x 128B = 16384
#define ATT_K 16384      // 64 x 128B  =  8192
#define ATT_V 24576      //               8192

__global__ __launch_bounds__(256, 2)
void attn_kernel(const __half* __restrict__ q16,
                 const __half* __restrict__ k16,
                 const __half* __restrict__ v16,
                 __half* __restrict__ o16)
{
    __shared__ char smem[32768];
    uint32_t sb = smem_u32(smem);

    int q0    = ((int)gridDim.x - 1 - (int)blockIdx.x) * 128;  // longest first
    int head  = blockIdx.y;
    int batch = blockIdx.z;
    int tid   = threadIdx.x;
    int lane  = tid & 31;
    int wm    = tid >> 5;
    size_t tokbase = (size_t)batch * SS;

    // ---- stage Q tile (128 x 64 fp16), swizzled ----
    #pragma unroll
    for (int i = 0; i < 4; i++) {
        int e   = tid + i * 256;           // 0..1023
        int row = e >> 3;
        int seg = e & 7;
        uint32_t off = (uint32_t)row * 128 + ((seg ^ (row & 7)) << 4);
        cp16(sb + ATT_Q + off,
             q16 + (tokbase + q0 + row) * HH + head * DD + seg * 8);
    }
    CP_COMMIT(); CP_WAIT0();
    __syncthreads();

    // ---- extract Q A-fragments (4 k16-chunks) ----
    uint32_t qf[4][4];
    {
        int mrow = wm * 16 + (lane & 7) + ((lane >> 3) & 1) * 8;
        #pragma unroll
        for (int kc = 0; kc < 4; kc++) {
            int chunk = kc * 2 + (lane >> 4);
            uint32_t off = (uint32_t)mrow * 128 + ((chunk ^ (mrow & 7)) << 4);
            ldsm4(qf[kc], sb + ATT_Q + off);
        }
    }

    float o[8][4];
    #pragma unroll
    for (int j = 0; j < 8; j++)
        #pragma unroll
        for (int c = 0; c < 4; c++) o[j][c] = 0.0f;
    float m0 = -INFINITY, m1 = -INFINITY, l0 = 0.0f, l1 = 0.0f;

    int grp  = lane >> 2;
    int qr0  = q0 + wm * 16 + grp;
    int qr1  = qr0 + 8;
    int colb = (lane & 3) * 2;

    int nt = q0 / 64 + 2;
    for (int kt = 0; kt < nt; ++kt) {
        int k0 = kt * 64;
        __syncthreads();                       // prev tile compute done
        #pragma unroll
        for (int i = 0; i < 4; i++) {
            int e   = tid + i * 256;           // 0..1023: K then V
            int row = (e >> 3) & 63;
            int seg = e & 7;
            uint32_t off = (uint32_t)row * 128 + ((seg ^ (row & 7)) << 4);
            const __half* src = ((e >> 9) ? v16 : k16)
                              + (tokbase + k0 + row) * DD + seg * 8;
            cp16(sb + ((e >> 9) ? ATT_V : ATT_K) + off, src);
        }
        CP_COMMIT(); CP_WAIT0();
        __syncthreads();

        if (k0 > q0 + wm * 16 + 15) continue;  // warp fully masked

        // ---- scores ----
        float s[8][4];
        #pragma unroll
        for (int j = 0; j < 8; j++)
            #pragma unroll
            for (int c = 0; c < 4; c++) s[j][c] = 0.0f;
        {
            int keyrow = (lane & 7) + ((lane >> 4) & 1) * 8;
            int kchalf = (lane >> 3) & 1;
            #pragma unroll
            for (int nb = 0; nb < 4; nb++) {
                int key = nb * 16 + keyrow;
                #pragma unroll
                for (int kc = 0; kc < 4; kc++) {
                    int chunk = kc * 2 + kchalf;
                    uint32_t off = (uint32_t)key * 128 + ((chunk ^ (key & 7)) << 4);
                    uint32_t kf[4];
                    ldsm4(kf, sb + ATT_K + off);
                    mma_f16(s[nb * 2 + 0], qf[kc], kf[0], kf[1]);
                    mma_f16(s[nb * 2 + 1], qf[kc], kf[2], kf[3]);
                }
            }
        }

        // ---- causal mask ----
        if (k0 + 63 > qr0) {
            #pragma unroll
            for (int j = 0; j < 8; j++) {
                int key0 = k0 + j * 8 + colb;
                if (key0     > qr0) s[j][0] = -INFINITY;
                if (key0 + 1 > qr0) s[j][1] = -INFINITY;
                if (key0     > qr1) s[j][2] = -INFINITY;
                if (key0 + 1 > qr1) s[j][3] = -INFINITY;
            }
        }

        // ---- online softmax ----
        float mt0 = -INFINITY, mt1 = -INFINITY;
        #pragma unroll
        for (int j = 0; j < 8; j++) {
            mt0 = fmaxf(mt0, fmaxf(s[j][0], s[j][1]));
            mt1 = fmaxf(mt1, fmaxf(s[j][2], s[j][3]));
        }
        mt0 = fmaxf(mt0, __shfl_xor_sync(0xFFFFFFFFu, mt0, 1));
        mt0 = fmaxf(mt0, __shfl_xor_sync(0xFFFFFFFFu, mt0, 2));
        mt1 = fmaxf(mt1, __shfl_xor_sync(0xFFFFFFFFu, mt1, 1));
        mt1 = fmaxf(mt1, __shfl_xor_sync(0xFFFFFFFFu, mt1, 2));

        float mn0 = fmaxf(m0, mt0), mn1 = fmaxf(m1, mt1);
        float c0 = __expf(m0 - mn0), c1 = __expf(m1 - mn1);
        float ps0 = 0.0f, ps1 = 0.0f;
        #pragma unroll
        for (int j = 0; j < 8; j++) {
            s[j][0] = __expf(s[j][0] - mn0);
            s[j][1] = __expf(s[j][1] - mn0);
            s[j][2] = __expf(s[j][2] - mn1);
            s[j][3] = __expf(s[j][3] - mn1);
            ps0 += s[j][0] + s[j][1];
            ps1 += s[j][2] + s[j][3];
        }
        ps0 += __shfl_xor_sync(0xFFFFFFFFu, ps0, 1);
        ps0 += __shfl_xor_sync(0xFFFFFFFFu, ps0, 2);
        ps1 += __shfl_xor_sync(0xFFFFFFFFu, ps1, 1);
        ps1 += __shfl_xor_sync(0xFFFFFFFFu, ps1, 2);
        l0 = l0 * c0 + ps0;
        l1 = l1 * c1 + ps1;
        m0 = mn0; m1 = mn1;
        #pragma unroll
        for (int j = 0; j < 8; j++) {
            o[j][0] *= c0; o[j][1] *= c0;
            o[j][2] *= c1; o[j][3] *= c1;
        }

        // ---- P fragments (register pack) ----
        uint32_t pf[4][4];
        #pragma unroll
        for (int kc = 0; kc < 4; kc++) {
            pf[kc][0] = h2pack(s[2 * kc][0],     s[2 * kc][1]);
            pf[kc][1] = h2pack(s[2 * kc][2],     s[2 * kc][3]);
            pf[kc][2] = h2pack(s[2 * kc + 1][0], s[2 * kc + 1][1]);
            pf[kc][3] = h2pack(s[2 * kc + 1][2], s[2 * kc + 1][3]);
        }

        // ---- O += P @ V (V via trans ldsm) ----
        {
            int keyrow = (lane & 7) + ((lane >> 3) & 1) * 8;
            int dchalf = (lane >> 4) & 1;
            #pragma unroll
            for (int dnb = 0; dnb < 4; dnb++) {
                #pragma unroll
                for (int kc = 0; kc < 4; kc++) {
                    int key = kc * 16 + keyrow;
                    int chunk = dnb * 2 + dchalf;
                    uint32_t off = (uint32_t)key * 128 + ((chunk ^ (key & 7)) << 4);
                    uint32_t vf[4];
                    ldsm4t(vf, sb + ATT_V + off);
                    mma_f16(o[dnb * 2 + 0], pf[kc], vf[0], vf[1]);
                    mma_f16(o[dnb * 2 + 1], pf[kc], vf[2], vf[3]);
                }
            }
        }
    }

    float inv0 = 1.0f / l0, inv1 = 1.0f / l1;
    size_t ob0 = (tokbase + qr0) * HH + head * DD;
    size_t ob1 = (tokbase + qr1) * HH + head * DD;
    #pragma unroll
    for (int j = 0; j < 8; j++) {
        int dim = j * 8 + colb;
        *(uint32_t*)(o16 + ob0 + dim) = h2pack(o[j][0] * inv0, o[j][1] * inv0);
        *(uint32_t*)(o16 + ob1 + dim) = h2pack(o[j][2] * inv1, o[j][3] * inv1);
    }
}

// ------------------------------- driver -------------------------------------
extern "C" void kernel_launch(void* const* d_in, const int* in_sizes, int n_in,
                              void* d_out, int out_size)
{
    const int*   ids     = (const int*)  d_in[0];
    const int*   pos     = (const int*)  d_in[1];
    const float* wte     = (const float*)d_in[2];
    const float* wpe     = (const float*)d_in[3];
    const float* ln1_w   = (const float*)d_in[4];
    const float* ln1_b   = (const float*)d_in[5];
    const float* cattn_w = (const float*)d_in[6];
    const float* cattn_b = (const float*)d_in[7];
    const float* cproj_w = (const float*)d_in[8];
    const float* cproj_b = (const float*)d_in[9];
    const float* ln2_w   = (const float*)d_in[10];
    const float* ln2_b   = (const float*)d_in[11];
    const float* fc_w    = (const float*)d_in[12];
    const float* fc_b    = (const float*)d_in[13];
    const float* mproj_w = (const float*)d_in[14];
    const float* mproj_b = (const float*)d_in[15];
    const float* lnf_w   = (const float*)d_in[16];
    const float* lnf_b   = (const float*)d_in[17];
    float* out = (float*)d_out;

    float *h;
    __half *wq_h, *wq_l, *wc_h, *wc_l, *wf_h, *wf_l, *wm_h, *wm_l;
    __half *x16, *at16, *m16, *q16, *k16, *v16;
    cudaGetSymbolAddress((void**)&h,    g_h);
    cudaGetSymbolAddress((void**)&wq_h, g_wq_h); cudaGetSymbolAddress((void**)&wq_l, g_wq_l);
    cudaGetSymbolAddress((void**)&wc_h, g_wc_h); cudaGetSymbolAddress((void**)&wc_l, g_wc_l);
    cudaGetSymbolAddress((void**)&wf_h, g_wf_h); cudaGetSymbolAddress((void**)&wf_l, g_wf_l);
    cudaGetSymbolAddress((void**)&wm_h, g_wm_h); cudaGetSymbolAddress((void**)&wm_l, g_wm_l);
    cudaGetSymbolAddress((void**)&x16,  g_x16);
    cudaGetSymbolAddress((void**)&at16, g_at16);
    cudaGetSymbolAddress((void**)&m16,  g_m16);
    cudaGetSymbolAddress((void**)&q16,  g_q16);
    cudaGetSymbolAddress((void**)&k16,  g_k16);
    cudaGetSymbolAddress((void**)&v16,  g_v16);

    cudaFuncSetAttribute(gemm_f16<1>, cudaFuncAttributeMaxDynamicSharedMemorySize, GEMM_SMEM);
    cudaFuncSetAttribute(gemm_f16<2>, cudaFuncAttributeMaxDynamicSharedMemorySize, GEMM_SMEM);
    cudaFuncSetAttribute(gemm_f16<3>, cudaFuncAttributeMaxDynamicSharedMemorySize, GEMM_SMEM);

    split_all_kernel<<<NTOT4 / 256, 256>>>(cattn_w, cproj_w, fc_w, mproj_w,
                                           wq_h, wq_l, wc_h, wc_l,
                                           wf_h, wf_l, wm_h, wm_l);

    embed_kernel<<<MTOK, 256>>>(ids, pos, wte, wpe, h);

    for (int l = 0; l < LL; ++l) {
        ln_kernel<true><<<MTOK, 256>>>(h, ln1_w + (size_t)l * HH,
                                       ln1_b + (size_t)l * HH, x16, nullptr);

        gemm_f16<3><<<dim3(QKVW / 128, MTOK / 128), 256, GEMM_SMEM>>>(
            x16, wq_h + (size_t)l * QKVW * HH, wq_l + (size_t)l * QKVW * HH,
            cattn_b + (size_t)l * QKVW, nullptr, nullptr, q16, k16, v16,
            MTOK, QKVW, HH);

        attn_kernel<<<dim3(SS / 128, NHEAD, BB), 256>>>(q16, k16, v16, at16);

        gemm_f16<1><<<dim3(HH / 128, MTOK / 128), 256, GEMM_SMEM>>>(
            at16, wc_h + (size_t)l * HH * HH, wc_l + (size_t)l * HH * HH,
            cproj_b + (size_t)l * HH, h, h, nullptr, nullptr, nullptr,
            MTOK, HH, HH);

        ln_kernel<true><<<MTOK, 256>>>(h, ln2_w + (size_t)l * HH,
                                       ln2_b + (size_t)l * HH, x16, nullptr);

        gemm_f16<2><<<dim3(II / 128, MTOK / 128), 256, GEMM_SMEM>>>(
            x16, wf_h + (size_t)l * II * HH, wf_l + (size_t)l * II * HH,
            fc_b + (size_t)l * II, nullptr, nullptr, m16, nullptr, nullptr,
            MTOK, II, HH);

        gemm_f16<1><<<dim3(HH / 128, MTOK / 128), 256, GEMM_SMEM>>>(
            m16, wm_h + (size_t)l * HH * II, wm_l + (size_t)l * HH * II,
            mproj_b + (size_t)l * HH, h, h, nullptr, nullptr, nullptr,
            MTOK, HH, II);
    }

    ln_kernel<false><<<MTOK, 256>>>(h, lnf_w, lnf_b, nullptr, out);
}